// round 2
// baseline (speedup 1.0000x reference)
#include <cuda_runtime.h>
#include <cuda_bf16.h>
#include <math.h>

#define N_NODES 50000
#define N_EDGES 800000
#define F_IN    128
#define HF      128     // H*F
#define NHEADS  8
#define FPH     16
#define NEG_SLOPE 0.2f

// ---------------- scratch (static device globals; no allocation) ----------------
__device__ float g_h[N_NODES * HF];        // projected features [N,128]
__device__ float g_asrc[N_NODES * NHEADS]; // per-node src logits
__device__ float g_adst[N_NODES * NHEADS]; // per-node dst logits
__device__ int   g_deg[N_NODES];
__device__ int   g_off[N_NODES + 1];
__device__ int   g_cursor[N_NODES];
__device__ int   g_csrc[N_EDGES];          // CSR: source node per slot
__device__ float g_e[N_EDGES * NHEADS];    // CSR: leaky-relu'd edge scores
__device__ int   g_is64;                   // 1 if edge_index is int64, 0 if int32

// ---------------- kernel -1: probe edge_index dtype ----------------
// If the buffer really holds int64 indices, every value is in [0, N_NODES).
// If it holds int32 pairs, the int64 view packs a random index into the high
// word -> value >= 2^32 with overwhelming probability over 256 samples.
__global__ void detect_kernel(const void* ei_raw) {
    if (threadIdx.x != 0 || blockIdx.x != 0) return;
    const long long* e64 = (const long long*)ei_raw;
    int ok = 1;
    for (int i = 0; i < 256; i++) {
        long long v = e64[i];
        if (v < 0 || v >= N_NODES) { ok = 0; break; }
    }
    g_is64 = ok;
}

__device__ __forceinline__ void load_edge(const void* ei_raw, int e, int& s, int& d) {
    if (g_is64) {
        const long long* p = (const long long*)ei_raw;
        s = (int)p[e];
        d = (int)p[N_EDGES + e];
    } else {
        const int* p = (const int*)ei_raw;
        s = p[e];
        d = p[N_EDGES + e];
    }
}

// ---------------- kernel 0: zero the atomically-accumulated buffers ----------------
__global__ void zero_kernel() {
    int i = blockIdx.x * blockDim.x + threadIdx.x;
    int total = N_NODES * NHEADS;
    if (i < total) { g_asrc[i] = 0.f; g_adst[i] = 0.f; }
    if (i < N_NODES) g_deg[i] = 0;
}

// ---------------- kernel 1: tiled GEMM h = x @ W^T, fused a_src/a_dst epilogue ----
// block tile: 64 nodes x 128 cols, K-tile 16, 512 threads, 4x4 per thread.
#define TM 64
#define KT 16
__global__ __launch_bounds__(512) void gemm_kernel(
    const float* __restrict__ x, const float* __restrict__ W,
    const float* __restrict__ att_src, const float* __restrict__ att_dst)
{
    __shared__ float xs[KT][TM];    // 4KB  (k-major)
    __shared__ float ws[KT][HF];    // 8KB  (k-major)
    int t  = threadIdx.x;
    int ty = t >> 5;        // 0..15  -> nodes ty*4..ty*4+3
    int tx = t & 31;        // 0..31  -> cols  tx*4..tx*4+3
    int m0 = blockIdx.x * TM;

    float acc[4][4] = {};

    for (int k0 = 0; k0 < F_IN; k0 += KT) {
        // load x tile (64x16), 2 elems/thread
        {
            int r  = t >> 3;          // 0..63
            int kk = (t & 7) * 2;     // 0,2,..,14
            int gm = m0 + r;
            float v0 = 0.f, v1 = 0.f;
            if (gm < N_NODES) {
                v0 = x[gm * F_IN + k0 + kk];
                v1 = x[gm * F_IN + k0 + kk + 1];
            }
            xs[kk][r] = v0;
            xs[kk + 1][r] = v1;
        }
        // load W tile (128x16), 4 elems/thread (W is [128,128] row-major, cols of h)
        {
            int c  = t >> 2;          // 0..127
            int kk = (t & 3) * 4;     // 0,4,8,12
            float4 wv = *(const float4*)&W[c * F_IN + k0 + kk];
            ws[kk][c] = wv.x; ws[kk + 1][c] = wv.y;
            ws[kk + 2][c] = wv.z; ws[kk + 3][c] = wv.w;
        }
        __syncthreads();
        #pragma unroll
        for (int kk = 0; kk < KT; kk++) {
            float4 xf = *(const float4*)&xs[kk][ty * 4];
            float4 wf = *(const float4*)&ws[kk][tx * 4];
            acc[0][0] += xf.x * wf.x; acc[0][1] += xf.x * wf.y; acc[0][2] += xf.x * wf.z; acc[0][3] += xf.x * wf.w;
            acc[1][0] += xf.y * wf.x; acc[1][1] += xf.y * wf.y; acc[1][2] += xf.y * wf.z; acc[1][3] += xf.y * wf.w;
            acc[2][0] += xf.z * wf.x; acc[2][1] += xf.z * wf.y; acc[2][2] += xf.z * wf.z; acc[2][3] += xf.z * wf.w;
            acc[3][0] += xf.w * wf.x; acc[3][1] += xf.w * wf.y; acc[3][2] += xf.w * wf.z; acc[3][3] += xf.w * wf.w;
        }
        __syncthreads();
    }

    // epilogue: store h, accumulate per-head logits
    int h     = tx >> 2;          // head (4 cols always inside one head)
    int fbase = (tx & 3) * 4;     // feature offset inside the head
    float as0 = att_src[h * FPH + fbase + 0];
    float as1 = att_src[h * FPH + fbase + 1];
    float as2 = att_src[h * FPH + fbase + 2];
    float as3 = att_src[h * FPH + fbase + 3];
    float ad0 = att_dst[h * FPH + fbase + 0];
    float ad1 = att_dst[h * FPH + fbase + 1];
    float ad2 = att_dst[h * FPH + fbase + 2];
    float ad3 = att_dst[h * FPH + fbase + 3];

    #pragma unroll
    for (int i = 0; i < 4; i++) {
        int gm = m0 + ty * 4 + i;
        if (gm < N_NODES) {
            float4 hv = make_float4(acc[i][0], acc[i][1], acc[i][2], acc[i][3]);
            *(float4*)&g_h[gm * HF + tx * 4] = hv;
            float ps = acc[i][0]*as0 + acc[i][1]*as1 + acc[i][2]*as2 + acc[i][3]*as3;
            float pd = acc[i][0]*ad0 + acc[i][1]*ad1 + acc[i][2]*ad2 + acc[i][3]*ad3;
            atomicAdd(&g_asrc[gm * NHEADS + h], ps);
            atomicAdd(&g_adst[gm * NHEADS + h], pd);
        }
    }
}

// ---------------- kernel 2: in-degree histogram ----------------
__global__ void deg_kernel(const void* __restrict__ ei) {
    int e = blockIdx.x * blockDim.x + threadIdx.x;
    if (e >= N_EDGES) return;
    int s, d;
    load_edge(ei, e, s, d);
    atomicAdd(&g_deg[d], 1);
}

// ---------------- kernel 3: single-block exclusive scan -> offsets + cursors ------
#define SCAN_T 1024
#define CHUNK  49   // 1024*49 = 50176 >= 50000
__global__ __launch_bounds__(SCAN_T) void scan_kernel() {
    __shared__ int sums[SCAN_T];
    int t = threadIdx.x;
    int base = t * CHUNK;
    int s = 0;
    for (int k = 0; k < CHUNK; k++) {
        int idx = base + k;
        if (idx < N_NODES) s += g_deg[idx];
    }
    sums[t] = s;
    __syncthreads();
    for (int off = 1; off < SCAN_T; off <<= 1) {
        int v = 0;
        if (t >= off) v = sums[t - off];
        __syncthreads();
        sums[t] += v;
        __syncthreads();
    }
    int run = (t == 0) ? 0 : sums[t - 1];
    for (int k = 0; k < CHUNK; k++) {
        int idx = base + k;
        if (idx < N_NODES) {
            g_off[idx]    = run;
            g_cursor[idx] = run;
            run += g_deg[idx];
        }
    }
    if (t == 0) g_off[N_NODES] = N_EDGES;
}

// ---------------- kernel 4: scatter edges into CSR, materialize leaky scores ------
__device__ __forceinline__ float lrelu(float v) { return v >= 0.f ? v : NEG_SLOPE * v; }

__global__ void scatter_kernel(const void* __restrict__ ei) {
    int e = blockIdx.x * blockDim.x + threadIdx.x;
    if (e >= N_EDGES) return;
    int s, d;
    load_edge(ei, e, s, d);
    int pos = atomicAdd(&g_cursor[d], 1);
    float4 as0 = *(const float4*)&g_asrc[s * NHEADS];
    float4 as1 = *(const float4*)&g_asrc[s * NHEADS + 4];
    float4 ad0 = *(const float4*)&g_adst[d * NHEADS];
    float4 ad1 = *(const float4*)&g_adst[d * NHEADS + 4];
    float4 e0, e1;
    e0.x = lrelu(as0.x + ad0.x); e0.y = lrelu(as0.y + ad0.y);
    e0.z = lrelu(as0.z + ad0.z); e0.w = lrelu(as0.w + ad0.w);
    e1.x = lrelu(as1.x + ad1.x); e1.y = lrelu(as1.y + ad1.y);
    e1.z = lrelu(as1.z + ad1.z); e1.w = lrelu(as1.w + ad1.w);
    *(float4*)&g_e[pos * NHEADS]     = e0;
    *(float4*)&g_e[pos * NHEADS + 4] = e1;
    g_csrc[pos] = s;
}

// ---------------- kernel 5: per-node softmax + weighted aggregation --------------
// one warp per destination node; lanes 0..7 own one head each for the softmax,
// all 32 lanes cover the 128 output features (float4 per lane).
__global__ __launch_bounds__(256) void agg_kernel(
    const float* __restrict__ bias, float* __restrict__ out)
{
    int warp = (blockIdx.x * blockDim.x + threadIdx.x) >> 5;
    int lane = threadIdx.x & 31;
    if (warp >= N_NODES) return;
    int n   = warp;
    int beg = g_off[n];
    int end = g_off[n + 1];

    // phase 1: online max + sum per head (lanes 0..7)
    float m = -INFINITY, ssum = 0.f;
    if (lane < 8) {
        for (int j = beg; j < end; j++) {
            float ev = g_e[j * NHEADS + lane];
            float nm = fmaxf(m, ev);
            ssum = ssum * __expf(m - nm) + __expf(ev - nm);
            m = nm;
        }
    }
    float inv = 1.f / (ssum + 1e-16f);

    // phase 2: alpha-weighted gather of h[src]
    float4 acc = make_float4(0.f, 0.f, 0.f, 0.f);
    int hsel = lane >> 2;   // this lane's head (4 consecutive f per lane, same head)
    for (int j = beg; j < end; j++) {
        int src = g_csrc[j];
        float ev = (lane < 8) ? g_e[j * NHEADS + lane] : 0.f;
        float alpha = __expf(ev - m) * inv;   // garbage on lanes>=8, never read
        float a = __shfl_sync(0xffffffffu, alpha, hsel);
        float4 hv = *(const float4*)&g_h[src * HF + lane * 4];
        acc.x += a * hv.x; acc.y += a * hv.y;
        acc.z += a * hv.z; acc.w += a * hv.w;
    }

    float4 bv = *(const float4*)&bias[lane * 4];
    float4 o = make_float4(acc.x + bv.x, acc.y + bv.y, acc.z + bv.z, acc.w + bv.w);
    *(float4*)&out[n * HF + lane * 4] = o;
}

// ---------------- launch ----------------
extern "C" void kernel_launch(void* const* d_in, const int* in_sizes, int n_in,
                              void* d_out, int out_size)
{
    // Identify inputs by element count (robust to metadata ordering):
    //   x: 6,400,000   W: 16,384   edge_index: 1,600,000
    //   att_src / att_dst / bias: 128 each (relative order preserved)
    const float* x = nullptr;
    const float* W = nullptr;
    const void*  ei = nullptr;
    const float* p128[3] = {nullptr, nullptr, nullptr};
    int n128 = 0;
    for (int i = 0; i < n_in; i++) {
        long long sz = in_sizes[i];
        if (sz == (long long)N_NODES * F_IN)      x  = (const float*)d_in[i];
        else if (sz == (long long)HF * F_IN)      W  = (const float*)d_in[i];
        else if (sz == 2LL * N_EDGES)             ei = d_in[i];
        else if (sz == 128 && n128 < 3)           p128[n128++] = (const float*)d_in[i];
    }
    const float* att_src = p128[0];
    const float* att_dst = p128[1];
    const float* bias    = p128[2];
    float*       out     = (float*)d_out;

    detect_kernel<<<1, 32>>>(ei);
    int zt = N_NODES * NHEADS;   // covers deg too (N < N*8)
    zero_kernel<<<(zt + 255) / 256, 256>>>();
    gemm_kernel<<<(N_NODES + TM - 1) / TM, 512>>>(x, W, att_src, att_dst);
    deg_kernel<<<(N_EDGES + 255) / 256, 256>>>(ei);
    scan_kernel<<<1, SCAN_T>>>();
    scatter_kernel<<<(N_EDGES + 255) / 256, 256>>>(ei);
    agg_kernel<<<(N_NODES * 32 + 255) / 256, 256>>>(bias, out);
}

// round 3
// speedup vs baseline: 1.5778x; 1.5778x over previous
#include <cuda_runtime.h>
#include <cuda_bf16.h>
#include <math.h>

#define N_NODES 50000
#define N_EDGES 800000
#define F_IN    128
#define HF      128     // H*F
#define NHEADS  8
#define FPH     16
#define NEG_SLOPE 0.2f

// ---------------- scratch (static device globals; no allocation) ----------------
__device__ float g_h[N_NODES * HF];        // projected features [N,128]
__device__ float g_asrc[N_NODES * NHEADS]; // per-node src logits
__device__ float g_adst[N_NODES * NHEADS]; // per-node dst logits
__device__ int   g_deg[N_NODES];           // zero-initialized; re-zeroed by scanC each run
__device__ int   g_off[N_NODES + 1];
__device__ int   g_cursor[N_NODES];
__device__ int   g_bsums[128];
__device__ int   g_bpre[128];
__device__ int   g_csrc[N_EDGES];          // CSR: source node per slot
__device__ int   g_is64;                   // 1 if edge_index is int64, 0 if int32

__device__ __forceinline__ float lrelu(float v) { return v >= 0.f ? v : NEG_SLOPE * v; }

// ---------------- kernel: probe edge_index dtype ----------------
__global__ void detect_kernel(const void* ei_raw) {
    if (threadIdx.x != 0 || blockIdx.x != 0) return;
    const long long* e64 = (const long long*)ei_raw;
    int ok = 1;
    for (int i = 0; i < 256; i++) {
        long long v = e64[i];
        if (v < 0 || v >= N_NODES) { ok = 0; break; }
    }
    g_is64 = ok;
}

// ---------------- gemm: h = x @ W^T with fused per-head logit reduction ----------
#define TM 64
#define KT 16
__global__ __launch_bounds__(512) void gemm_kernel(
    const float* __restrict__ x, const float* __restrict__ W,
    const float* __restrict__ att_src, const float* __restrict__ att_dst)
{
    __shared__ float xs[KT][TM];
    __shared__ float ws[KT][HF];
    int t  = threadIdx.x;
    int ty = t >> 5;        // warp id: nodes ty*4..ty*4+3
    int tx = t & 31;        // lane: cols tx*4..tx*4+3
    int m0 = blockIdx.x * TM;

    float acc[4][4] = {};

    for (int k0 = 0; k0 < F_IN; k0 += KT) {
        {
            int r  = t >> 3;
            int kk = (t & 7) * 2;
            int gm = m0 + r;
            float v0 = 0.f, v1 = 0.f;
            if (gm < N_NODES) {
                v0 = x[gm * F_IN + k0 + kk];
                v1 = x[gm * F_IN + k0 + kk + 1];
            }
            xs[kk][r] = v0;
            xs[kk + 1][r] = v1;
        }
        {
            int c  = t >> 2;
            int kk = (t & 3) * 4;
            float4 wv = *(const float4*)&W[c * F_IN + k0 + kk];
            ws[kk][c] = wv.x; ws[kk + 1][c] = wv.y;
            ws[kk + 2][c] = wv.z; ws[kk + 3][c] = wv.w;
        }
        __syncthreads();
        #pragma unroll
        for (int kk = 0; kk < KT; kk++) {
            float4 xf = *(const float4*)&xs[kk][ty * 4];
            float4 wf = *(const float4*)&ws[kk][tx * 4];
            acc[0][0] += xf.x * wf.x; acc[0][1] += xf.x * wf.y; acc[0][2] += xf.x * wf.z; acc[0][3] += xf.x * wf.w;
            acc[1][0] += xf.y * wf.x; acc[1][1] += xf.y * wf.y; acc[1][2] += xf.y * wf.z; acc[1][3] += xf.y * wf.w;
            acc[2][0] += xf.z * wf.x; acc[2][1] += xf.z * wf.y; acc[2][2] += xf.z * wf.z; acc[2][3] += xf.z * wf.w;
            acc[3][0] += xf.w * wf.x; acc[3][1] += xf.w * wf.y; acc[3][2] += xf.w * wf.z; acc[3][3] += xf.w * wf.w;
        }
        __syncthreads();
    }

    // epilogue: store h; reduce per-head logits across the 4 lanes of each head
    int h     = tx >> 2;
    int fbase = (tx & 3) * 4;
    float as0 = att_src[h * FPH + fbase + 0];
    float as1 = att_src[h * FPH + fbase + 1];
    float as2 = att_src[h * FPH + fbase + 2];
    float as3 = att_src[h * FPH + fbase + 3];
    float ad0 = att_dst[h * FPH + fbase + 0];
    float ad1 = att_dst[h * FPH + fbase + 1];
    float ad2 = att_dst[h * FPH + fbase + 2];
    float ad3 = att_dst[h * FPH + fbase + 3];

    #pragma unroll
    for (int i = 0; i < 4; i++) {
        int gm = m0 + ty * 4 + i;       // warp-uniform condition
        if (gm < N_NODES) {
            float4 hv = make_float4(acc[i][0], acc[i][1], acc[i][2], acc[i][3]);
            *(float4*)&g_h[gm * HF + tx * 4] = hv;
            float ps = acc[i][0]*as0 + acc[i][1]*as1 + acc[i][2]*as2 + acc[i][3]*as3;
            float pd = acc[i][0]*ad0 + acc[i][1]*ad1 + acc[i][2]*ad2 + acc[i][3]*ad3;
            ps += __shfl_xor_sync(0xffffffffu, ps, 1);
            ps += __shfl_xor_sync(0xffffffffu, ps, 2);
            pd += __shfl_xor_sync(0xffffffffu, pd, 1);
            pd += __shfl_xor_sync(0xffffffffu, pd, 2);
            if ((tx & 3) == 0) {
                g_asrc[gm * NHEADS + h] = ps;
                g_adst[gm * NHEADS + h] = pd;
            }
        }
    }
}

// ---------------- deg histogram: 4 edges per thread, vector loads ----------------
__global__ void deg_kernel(const void* __restrict__ ei) {
    int i = (blockIdx.x * blockDim.x + threadIdx.x) * 4;
    if (i >= N_EDGES) return;
    int d0, d1, d2, d3;
    if (g_is64) {
        const longlong2* p = (const longlong2*)((const long long*)ei + N_EDGES + i);
        longlong2 a = p[0], b = p[1];
        d0 = (int)a.x; d1 = (int)a.y; d2 = (int)b.x; d3 = (int)b.y;
    } else {
        int4 a = *(const int4*)((const int*)ei + N_EDGES + i);
        d0 = a.x; d1 = a.y; d2 = a.z; d3 = a.w;
    }
    atomicAdd(&g_deg[d0], 1);
    atomicAdd(&g_deg[d1], 1);
    atomicAdd(&g_deg[d2], 1);
    atomicAdd(&g_deg[d3], 1);
}

// ---------------- 3-kernel coalesced scan ----------------
#define SB   512
#define NBLK 98     // 98*512 = 50176 >= 50000
__global__ __launch_bounds__(SB) void scanA_kernel() {
    __shared__ int s[SB];
    int t = threadIdx.x;
    int i = blockIdx.x * SB + t;
    int v = (i < N_NODES) ? g_deg[i] : 0;
    s[t] = v;
    __syncthreads();
    #pragma unroll
    for (int off = 1; off < SB; off <<= 1) {
        int u = (t >= off) ? s[t - off] : 0;
        __syncthreads();
        s[t] += u;
        __syncthreads();
    }
    if (i < N_NODES) g_off[i] = s[t] - v;    // exclusive, block-local
    if (t == SB - 1) g_bsums[blockIdx.x] = s[t];
}

__global__ __launch_bounds__(128) void scanB_kernel() {
    __shared__ int s[128];
    int t = threadIdx.x;
    int v = (t < NBLK) ? g_bsums[t] : 0;
    s[t] = v;
    __syncthreads();
    #pragma unroll
    for (int off = 1; off < 128; off <<= 1) {
        int u = (t >= off) ? s[t - off] : 0;
        __syncthreads();
        s[t] += u;
        __syncthreads();
    }
    if (t < NBLK) g_bpre[t] = s[t] - v;      // exclusive
}

__global__ __launch_bounds__(SB) void scanC_kernel() {
    int t = threadIdx.x;
    int i = blockIdx.x * SB + t;
    if (i < N_NODES) {
        int o = g_off[i] + g_bpre[blockIdx.x];
        g_off[i]    = o;
        g_cursor[i] = o;
        g_deg[i]    = 0;                     // reset for next graph replay
    }
    if (i == 0) g_off[N_NODES] = N_EDGES;
}

// ---------------- scatter: CSR slot assignment only ----------------
__global__ void scatter_kernel(const void* __restrict__ ei) {
    int e = blockIdx.x * blockDim.x + threadIdx.x;
    if (e >= N_EDGES) return;
    int s, d;
    if (g_is64) {
        const long long* p = (const long long*)ei;
        s = (int)p[e];
        d = (int)p[N_EDGES + e];
    } else {
        const int* p = (const int*)ei;
        s = p[e];
        d = p[N_EDGES + e];
    }
    int pos = atomicAdd(&g_cursor[d], 1);
    g_csrc[pos] = s;
}

// ---------------- agg: softmax (recomputed scores) + weighted gather -------------
// one warp per destination node.
// passes 1+2: lane = head (0..7) x edge-group (0..3); scores recomputed from
// asrc/adst (L2-resident), reduced across groups via shfl_xor.
// pass 3: all 32 lanes cover 128 features; alpha computed on lanes 0..7, shfl'd.
__global__ __launch_bounds__(256) void agg_kernel(
    const float* __restrict__ bias, float* __restrict__ out)
{
    int warp = (blockIdx.x * blockDim.x + threadIdx.x) >> 5;
    int lane = threadIdx.x & 31;
    if (warp >= N_NODES) return;
    int n   = warp;
    int beg = g_off[n];
    int end = g_off[n + 1];

    int head = lane & 7;
    int grp  = lane >> 3;
    float ad = g_adst[n * NHEADS + head];

    // pass 1: per-head max, 4 edges in flight
    float m = -INFINITY;
    for (int j = beg + grp; j < end; j += 4) {
        int src = g_csrc[j];
        float ev = lrelu(g_asrc[src * NHEADS + head] + ad);
        m = fmaxf(m, ev);
    }
    m = fmaxf(m, __shfl_xor_sync(0xffffffffu, m, 8));
    m = fmaxf(m, __shfl_xor_sync(0xffffffffu, m, 16));

    // pass 2: per-head sum of exp
    float ssum = 0.f;
    for (int j = beg + grp; j < end; j += 4) {
        int src = g_csrc[j];
        float ev = lrelu(g_asrc[src * NHEADS + head] + ad);
        ssum += __expf(ev - m);
    }
    ssum += __shfl_xor_sync(0xffffffffu, ssum, 8);
    ssum += __shfl_xor_sync(0xffffffffu, ssum, 16);
    float inv = 1.f / (ssum + 1e-16f);

    // pass 3: alpha-weighted gather, unrolled x2 for MLP
    float4 acc = make_float4(0.f, 0.f, 0.f, 0.f);
    int hsel = lane >> 2;
    int j = beg;
    for (; j + 1 < end; j += 2) {
        int src0 = g_csrc[j];
        int src1 = g_csrc[j + 1];
        float ev0 = (lane < 8) ? lrelu(g_asrc[src0 * NHEADS + lane] + ad) : 0.f;
        float ev1 = (lane < 8) ? lrelu(g_asrc[src1 * NHEADS + lane] + ad) : 0.f;
        float4 hv0 = *(const float4*)&g_h[src0 * HF + lane * 4];
        float4 hv1 = *(const float4*)&g_h[src1 * HF + lane * 4];
        float al0 = __expf(ev0 - m) * inv;
        float al1 = __expf(ev1 - m) * inv;
        float a0 = __shfl_sync(0xffffffffu, al0, hsel);
        float a1 = __shfl_sync(0xffffffffu, al1, hsel);
        acc.x += a0 * hv0.x; acc.y += a0 * hv0.y;
        acc.z += a0 * hv0.z; acc.w += a0 * hv0.w;
        acc.x += a1 * hv1.x; acc.y += a1 * hv1.y;
        acc.z += a1 * hv1.z; acc.w += a1 * hv1.w;
    }
    if (j < end) {
        int src = g_csrc[j];
        float ev = (lane < 8) ? lrelu(g_asrc[src * NHEADS + lane] + ad) : 0.f;
        float alpha = __expf(ev - m) * inv;
        float a = __shfl_sync(0xffffffffu, alpha, hsel);
        float4 hv = *(const float4*)&g_h[src * HF + lane * 4];
        acc.x += a * hv.x; acc.y += a * hv.y;
        acc.z += a * hv.z; acc.w += a * hv.w;
    }

    float4 bv = *(const float4*)&bias[lane * 4];
    float4 o = make_float4(acc.x + bv.x, acc.y + bv.y, acc.z + bv.z, acc.w + bv.w);
    *(float4*)&out[n * HF + lane * 4] = o;
}

// ---------------- launch ----------------
extern "C" void kernel_launch(void* const* d_in, const int* in_sizes, int n_in,
                              void* d_out, int out_size)
{
    const float* x = nullptr;
    const float* W = nullptr;
    const void*  ei = nullptr;
    const float* p128[3] = {nullptr, nullptr, nullptr};
    int n128 = 0;
    for (int i = 0; i < n_in; i++) {
        long long sz = in_sizes[i];
        if (sz == (long long)N_NODES * F_IN)      x  = (const float*)d_in[i];
        else if (sz == (long long)HF * F_IN)      W  = (const float*)d_in[i];
        else if (sz == 2LL * N_EDGES)             ei = d_in[i];
        else if (sz == 128 && n128 < 3)           p128[n128++] = (const float*)d_in[i];
    }
    const float* att_src = p128[0];
    const float* att_dst = p128[1];
    const float* bias    = p128[2];
    float*       out     = (float*)d_out;

    detect_kernel<<<1, 32>>>(ei);
    gemm_kernel<<<(N_NODES + TM - 1) / TM, 512>>>(x, W, att_src, att_dst);
    deg_kernel<<<(N_EDGES / 4 + 255) / 256, 256>>>(ei);
    scanA_kernel<<<NBLK, SB>>>();
    scanB_kernel<<<1, 128>>>();
    scanC_kernel<<<NBLK, SB>>>();
    scatter_kernel<<<(N_EDGES + 511) / 512, 512>>>(ei);
    agg_kernel<<<(N_NODES * 32 + 255) / 256, 256>>>(bias, out);
}

// round 4
// speedup vs baseline: 2.1221x; 1.3449x over previous
#include <cuda_runtime.h>
#include <cuda_bf16.h>
#include <math.h>

#define N_NODES 50000
#define N_EDGES 800000
#define F_IN    128
#define HF      128     // H*F
#define NHEADS  8
#define FPH     16
#define NEG_SLOPE 0.2f

// ---------------- scratch (static device globals; no allocation) ----------------
__device__ float g_h[N_NODES * HF];        // projected features [N,128]
__device__ float g_asrc[N_NODES * NHEADS]; // per-node src logits
__device__ float g_adst[N_NODES * NHEADS]; // per-node dst logits
__device__ int   g_deg[N_NODES];           // zero-initialized; re-zeroed by scanC each run
__device__ int   g_off[N_NODES + 1];
__device__ int   g_cursor[N_NODES];
__device__ int   g_bsums[128];
__device__ int   g_csrc[N_EDGES];          // CSR: source node per slot
__device__ int   g_is64;                   // 1 if edge_index is int64, 0 if int32

__device__ __forceinline__ float lrelu(float v) { return v >= 0.f ? v : NEG_SLOPE * v; }

// ---------------- kernel: probe edge_index dtype ----------------
__global__ void detect_kernel(const void* ei_raw) {
    if (threadIdx.x != 0 || blockIdx.x != 0) return;
    const long long* e64 = (const long long*)ei_raw;
    int ok = 1;
    for (int i = 0; i < 256; i++) {
        long long v = e64[i];
        if (v < 0 || v >= N_NODES) { ok = 0; break; }
    }
    g_is64 = ok;
}

// ---------------- tensor-core gemm: h = x @ W^T (bf16x3), fused logits ----------
// block = 256 threads (8 warps as 4Mx2N), block tile 128x128, k-chunk 32.
// Each fp32 operand is split hi+lo bf16; D += Ah*Bh + Ah*Bl + Al*Bh (fp32 acc).
#define SMS 20   // smem row stride in uints (40 bf16) -> conflict-free frags

__device__ __forceinline__ void cvt_split(float a, float b, unsigned& hi, unsigned& lo) {
    __nv_bfloat16 ah = __float2bfloat16(a), bh = __float2bfloat16(b);
    float ar = a - __bfloat162float(ah);
    float br = b - __bfloat162float(bh);
    __nv_bfloat16 al = __float2bfloat16(ar), bl = __float2bfloat16(br);
    hi = ((unsigned)__bfloat16_as_ushort(bh) << 16) | (unsigned)__bfloat16_as_ushort(ah);
    lo = ((unsigned)__bfloat16_as_ushort(bl) << 16) | (unsigned)__bfloat16_as_ushort(al);
}

#define MMA_BF16(acc, a, b0, b1)                                              \
    asm volatile("mma.sync.aligned.m16n8k16.row.col.f32.bf16.bf16.f32 "       \
                 "{%0,%1,%2,%3}, {%4,%5,%6,%7}, {%8,%9}, {%0,%1,%2,%3};"      \
                 : "+f"((acc)[0]), "+f"((acc)[1]), "+f"((acc)[2]), "+f"((acc)[3]) \
                 : "r"((a)[0]), "r"((a)[1]), "r"((a)[2]), "r"((a)[3]),        \
                   "r"(b0), "r"(b1))

__global__ __launch_bounds__(256) void gemm_mma_kernel(
    const float* __restrict__ x, const float* __restrict__ W,
    const float* __restrict__ att_src, const float* __restrict__ att_dst)
{
    __shared__ unsigned Ah[128][SMS], Al[128][SMS];   // x tile   [m][k-pairs]
    __shared__ unsigned Bh[128][SMS], Bl[128][SMS];   // W tile   [n][k-pairs]

    int t    = threadIdx.x;
    int lane = t & 31;
    int wid  = t >> 5;
    int wr   = wid & 3;          // M group (32 rows)
    int wc   = wid >> 2;         // N group (64 cols)
    int q    = lane & 3;
    int gr   = lane >> 2;        // 0..7
    int m0   = blockIdx.x * 128;

    float acc[2][8][4];
    #pragma unroll
    for (int a = 0; a < 2; a++)
        #pragma unroll
        for (int b = 0; b < 8; b++)
            #pragma unroll
            for (int c = 0; c < 4; c++) acc[a][b][c] = 0.f;

    for (int ch = 0; ch < 4; ch++) {
        int k0 = ch * 32;
        __syncthreads();
        // load + convert x and W k-slices (each 128 rows x 8 float4)
        #pragma unroll
        for (int i = 0; i < 4; i++) {
            int idx = t + 256 * i;       // 0..1023
            int row = idx >> 3;
            int kq  = idx & 7;
            // x
            int gm = m0 + row;
            float4 v = make_float4(0.f, 0.f, 0.f, 0.f);
            if (gm < N_NODES) v = *(const float4*)&x[gm * F_IN + k0 + kq * 4];
            unsigned h0, l0, h1, l1;
            cvt_split(v.x, v.y, h0, l0);
            cvt_split(v.z, v.w, h1, l1);
            Ah[row][kq * 2] = h0; Ah[row][kq * 2 + 1] = h1;
            Al[row][kq * 2] = l0; Al[row][kq * 2 + 1] = l1;
            // W (row = n)
            float4 wv = *(const float4*)&W[row * F_IN + k0 + kq * 4];
            cvt_split(wv.x, wv.y, h0, l0);
            cvt_split(wv.z, wv.w, h1, l1);
            Bh[row][kq * 2] = h0; Bh[row][kq * 2 + 1] = h1;
            Bl[row][kq * 2] = l0; Bl[row][kq * 2 + 1] = l1;
        }
        __syncthreads();

        #pragma unroll
        for (int step = 0; step < 2; step++) {
            int kw = step * 8 + q;
            unsigned ah[2][4], al[2][4];
            #pragma unroll
            for (int mt = 0; mt < 2; mt++) {
                int r = wr * 32 + mt * 16 + gr;
                ah[mt][0] = Ah[r][kw];     ah[mt][1] = Ah[r + 8][kw];
                ah[mt][2] = Ah[r][kw + 4]; ah[mt][3] = Ah[r + 8][kw + 4];
                al[mt][0] = Al[r][kw];     al[mt][1] = Al[r + 8][kw];
                al[mt][2] = Al[r][kw + 4]; al[mt][3] = Al[r + 8][kw + 4];
            }
            #pragma unroll
            for (int nt = 0; nt < 8; nt++) {
                int n = wc * 64 + nt * 8 + gr;
                unsigned b0h = Bh[n][kw], b1h = Bh[n][kw + 4];
                unsigned b0l = Bl[n][kw], b1l = Bl[n][kw + 4];
                #pragma unroll
                for (int mt = 0; mt < 2; mt++) {
                    MMA_BF16(acc[mt][nt], ah[mt], b0h, b1h);
                    MMA_BF16(acc[mt][nt], ah[mt], b0l, b1l);
                    MMA_BF16(acc[mt][nt], al[mt], b0h, b1h);
                }
            }
        }
    }

    // epilogue: store h + fused per-head logit dot products
    float2 asv[8], adv[8];
    #pragma unroll
    for (int nt = 0; nt < 8; nt++) {
        int head = wc * 4 + (nt >> 1);
        int fc   = (nt & 1) * 8 + q * 2;
        asv[nt] = *(const float2*)&att_src[head * FPH + fc];
        adv[nt] = *(const float2*)&att_dst[head * FPH + fc];
    }

    #pragma unroll
    for (int mt = 0; mt < 2; mt++) {
        int m = m0 + wr * 32 + mt * 16 + gr;
        bool ok0 = (m < N_NODES), ok1 = (m + 8 < N_NODES);
        float ps0[4] = {0,0,0,0}, ps1[4] = {0,0,0,0};
        float pd0[4] = {0,0,0,0}, pd1[4] = {0,0,0,0};
        #pragma unroll
        for (int nt = 0; nt < 8; nt++) {
            float* c = acc[mt][nt];
            int n = wc * 64 + nt * 8 + q * 2;
            if (ok0) *(float2*)&g_h[m * HF + n]       = make_float2(c[0], c[1]);
            if (ok1) *(float2*)&g_h[(m + 8) * HF + n] = make_float2(c[2], c[3]);
            int hh = nt >> 1;
            ps0[hh] += c[0] * asv[nt].x + c[1] * asv[nt].y;
            pd0[hh] += c[0] * adv[nt].x + c[1] * adv[nt].y;
            ps1[hh] += c[2] * asv[nt].x + c[3] * asv[nt].y;
            pd1[hh] += c[2] * adv[nt].x + c[3] * adv[nt].y;
        }
        #pragma unroll
        for (int hh = 0; hh < 4; hh++) {
            ps0[hh] += __shfl_xor_sync(0xffffffffu, ps0[hh], 1);
            ps0[hh] += __shfl_xor_sync(0xffffffffu, ps0[hh], 2);
            pd0[hh] += __shfl_xor_sync(0xffffffffu, pd0[hh], 1);
            pd0[hh] += __shfl_xor_sync(0xffffffffu, pd0[hh], 2);
            ps1[hh] += __shfl_xor_sync(0xffffffffu, ps1[hh], 1);
            ps1[hh] += __shfl_xor_sync(0xffffffffu, ps1[hh], 2);
            pd1[hh] += __shfl_xor_sync(0xffffffffu, pd1[hh], 1);
            pd1[hh] += __shfl_xor_sync(0xffffffffu, pd1[hh], 2);
        }
        if (q == 0) {
            if (ok0) {
                *(float4*)&g_asrc[m * NHEADS + wc * 4] = make_float4(ps0[0], ps0[1], ps0[2], ps0[3]);
                *(float4*)&g_adst[m * NHEADS + wc * 4] = make_float4(pd0[0], pd0[1], pd0[2], pd0[3]);
            }
            if (ok1) {
                *(float4*)&g_asrc[(m + 8) * NHEADS + wc * 4] = make_float4(ps1[0], ps1[1], ps1[2], ps1[3]);
                *(float4*)&g_adst[(m + 8) * NHEADS + wc * 4] = make_float4(pd1[0], pd1[1], pd1[2], pd1[3]);
            }
        }
    }
}

// ---------------- deg histogram: 4 edges per thread, vector loads ----------------
__global__ void deg_kernel(const void* __restrict__ ei) {
    int i = (blockIdx.x * blockDim.x + threadIdx.x) * 4;
    if (i >= N_EDGES) return;
    int d0, d1, d2, d3;
    if (g_is64) {
        const longlong2* p = (const longlong2*)((const long long*)ei + N_EDGES + i);
        longlong2 a = p[0], b = p[1];
        d0 = (int)a.x; d1 = (int)a.y; d2 = (int)b.x; d3 = (int)b.y;
    } else {
        int4 a = *(const int4*)((const int*)ei + N_EDGES + i);
        d0 = a.x; d1 = a.y; d2 = a.z; d3 = a.w;
    }
    atomicAdd(&g_deg[d0], 1);
    atomicAdd(&g_deg[d1], 1);
    atomicAdd(&g_deg[d2], 1);
    atomicAdd(&g_deg[d3], 1);
}

// ---------------- 2-kernel coalesced scan ----------------
#define SB   512
#define NBLK 98     // 98*512 = 50176 >= 50000
__global__ __launch_bounds__(SB) void scanA_kernel() {
    __shared__ int s[SB];
    int t = threadIdx.x;
    int i = blockIdx.x * SB + t;
    int v = (i < N_NODES) ? g_deg[i] : 0;
    s[t] = v;
    __syncthreads();
    #pragma unroll
    for (int off = 1; off < SB; off <<= 1) {
        int u = (t >= off) ? s[t - off] : 0;
        __syncthreads();
        s[t] += u;
        __syncthreads();
    }
    if (i < N_NODES) g_off[i] = s[t] - v;    // exclusive, block-local
    if (t == SB - 1) g_bsums[blockIdx.x] = s[t];
}

__global__ __launch_bounds__(SB) void scanC_kernel() {
    __shared__ int s[128];
    int t = threadIdx.x;
    if (t < 128) s[t] = (t < NBLK) ? g_bsums[t] : 0;
    __syncthreads();
    #pragma unroll
    for (int off = 1; off < 128; off <<= 1) {
        int u = (t >= off && t < 128) ? s[t - off] : 0;
        __syncthreads();
        if (t < 128) s[t] += u;
        __syncthreads();
    }
    int excl = (blockIdx.x == 0) ? 0 : s[blockIdx.x - 1];
    int i = blockIdx.x * SB + t;
    if (i < N_NODES) {
        int o = g_off[i] + excl;
        g_off[i]    = o;
        g_cursor[i] = o;
        g_deg[i]    = 0;                     // reset for next graph replay
    }
    if (i == 0) g_off[N_NODES] = N_EDGES;
}

// ---------------- scatter: CSR slot assignment only ----------------
__global__ void scatter_kernel(const void* __restrict__ ei) {
    int e = blockIdx.x * blockDim.x + threadIdx.x;
    if (e >= N_EDGES) return;
    int s, d;
    if (g_is64) {
        const long long* p = (const long long*)ei;
        s = (int)p[e];
        d = (int)p[N_EDGES + e];
    } else {
        const int* p = (const int*)ei;
        s = p[e];
        d = p[N_EDGES + e];
    }
    int pos = atomicAdd(&g_cursor[d], 1);
    g_csrc[pos] = s;
}

// ---------------- agg: online softmax (1 pass) + weighted gather -----------------
__global__ __launch_bounds__(256) void agg_kernel(
    const float* __restrict__ bias, float* __restrict__ out)
{
    int warp = (blockIdx.x * blockDim.x + threadIdx.x) >> 5;
    int lane = threadIdx.x & 31;
    if (warp >= N_NODES) return;
    int n   = warp;
    int beg = g_off[n];
    int end = g_off[n + 1];

    int head = lane & 7;
    int grp  = lane >> 3;
    float ad = g_adst[n * NHEADS + head];

    // pass 1: online max+sum per (head, group), 4 edge-streams in flight
    float m = -INFINITY, ssum = 0.f;
    for (int j = beg + grp; j < end; j += 4) {
        int src = g_csrc[j];
        float ev = lrelu(g_asrc[src * NHEADS + head] + ad);
        float nm = fmaxf(m, ev);
        ssum = ssum * __expf(m - nm) + __expf(ev - nm);
        m = nm;
    }
    // merge the 4 groups (guarded against empty groups: m = -inf, ssum = 0)
    #pragma unroll
    for (int d = 8; d <= 16; d <<= 1) {
        float mo = __shfl_xor_sync(0xffffffffu, m, d);
        float so = __shfl_xor_sync(0xffffffffu, ssum, d);
        float nm = fmaxf(m, mo);
        float f1 = (ssum > 0.f) ? __expf(m - nm) : 0.f;
        float f2 = (so   > 0.f) ? __expf(mo - nm) : 0.f;
        ssum = ssum * f1 + so * f2;
        m = nm;
    }
    float inv = 1.f / (ssum + 1e-16f);

    // pass 2: alpha-weighted gather, unrolled x2 for MLP
    float4 acc = make_float4(0.f, 0.f, 0.f, 0.f);
    int hsel = lane >> 2;
    int j = beg;
    for (; j + 1 < end; j += 2) {
        int src0 = g_csrc[j];
        int src1 = g_csrc[j + 1];
        float ev0 = (lane < 8) ? lrelu(g_asrc[src0 * NHEADS + lane] + ad) : 0.f;
        float ev1 = (lane < 8) ? lrelu(g_asrc[src1 * NHEADS + lane] + ad) : 0.f;
        float4 hv0 = *(const float4*)&g_h[src0 * HF + lane * 4];
        float4 hv1 = *(const float4*)&g_h[src1 * HF + lane * 4];
        float al0 = __expf(ev0 - m) * inv;
        float al1 = __expf(ev1 - m) * inv;
        float a0 = __shfl_sync(0xffffffffu, al0, hsel);
        float a1 = __shfl_sync(0xffffffffu, al1, hsel);
        acc.x += a0 * hv0.x; acc.y += a0 * hv0.y;
        acc.z += a0 * hv0.z; acc.w += a0 * hv0.w;
        acc.x += a1 * hv1.x; acc.y += a1 * hv1.y;
        acc.z += a1 * hv1.z; acc.w += a1 * hv1.w;
    }
    if (j < end) {
        int src = g_csrc[j];
        float ev = (lane < 8) ? lrelu(g_asrc[src * NHEADS + lane] + ad) : 0.f;
        float alpha = __expf(ev - m) * inv;
        float a = __shfl_sync(0xffffffffu, alpha, hsel);
        float4 hv = *(const float4*)&g_h[src * HF + lane * 4];
        acc.x += a * hv.x; acc.y += a * hv.y;
        acc.z += a * hv.z; acc.w += a * hv.w;
    }

    float4 bv = *(const float4*)&bias[lane * 4];
    float4 o = make_float4(acc.x + bv.x, acc.y + bv.y, acc.z + bv.z, acc.w + bv.w);
    *(float4*)&out[n * HF + lane * 4] = o;
}

// ---------------- launch ----------------
extern "C" void kernel_launch(void* const* d_in, const int* in_sizes, int n_in,
                              void* d_out, int out_size)
{
    const float* x = nullptr;
    const float* W = nullptr;
    const void*  ei = nullptr;
    const float* p128[3] = {nullptr, nullptr, nullptr};
    int n128 = 0;
    for (int i = 0; i < n_in; i++) {
        long long sz = in_sizes[i];
        if (sz == (long long)N_NODES * F_IN)      x  = (const float*)d_in[i];
        else if (sz == (long long)HF * F_IN)      W  = (const float*)d_in[i];
        else if (sz == 2LL * N_EDGES)             ei = d_in[i];
        else if (sz == 128 && n128 < 3)           p128[n128++] = (const float*)d_in[i];
    }
    const float* att_src = p128[0];
    const float* att_dst = p128[1];
    const float* bias    = p128[2];
    float*       out     = (float*)d_out;

    detect_kernel<<<1, 32>>>(ei);
    gemm_mma_kernel<<<(N_NODES + 127) / 128, 256>>>(x, W, att_src, att_dst);
    deg_kernel<<<(N_EDGES / 4 + 255) / 256, 256>>>(ei);
    scanA_kernel<<<NBLK, SB>>>();
    scanC_kernel<<<NBLK, SB>>>();
    scatter_kernel<<<(N_EDGES + 511) / 512, 512>>>(ei);
    agg_kernel<<<(N_NODES * 32 + 255) / 256, 256>>>(bias, out);
}